// round 5
// baseline (speedup 1.0000x reference)
#include <cuda_runtime.h>
#include <cstdint>

// Problem constants (fixed by the reference setup)
#define BB   64
#define TT   1024
#define INC  16
#define NN   512
#define RR   16
#define OUTC 8
#define AA   0.1f   // DT / TAU

// Accurate-enough fast tanh: 1 - 2/(exp(2x)+1) via ex2.approx + rcp.approx.
// Error ~1e-6 (vs ~5e-4 for tanh.approx), safe for 1024-step recurrence.
__device__ __forceinline__ float fast_tanh(float x) {
    float e;
    asm("ex2.approx.f32 %0, %1;" : "=f"(e) : "f"(x * 2.885390082f)); // 2*log2(e)
    float r;
    asm("rcp.approx.f32 %0, %1;" : "=f"(r) : "f"(e + 1.0f));
    return fmaf(-2.0f, r, 1.0f);
}

// ---------------------------------------------------------------------------
// Kernel A: Inp[b,t,n] = sum_i X[b,t,i] * In_w[n,i]
// Written INTO the hidden output region of d_out (scratch aliasing: the scan
// reads Inp[b,t,:] at step t and overwrites the same slot with h_t).
// grid = B*T blocks, block = 512 threads (one n each). Memory-bound.
// ---------------------------------------------------------------------------
__global__ __launch_bounds__(NN) void inp_kernel(const float* __restrict__ x,
                                                 const float* __restrict__ inw,
                                                 float* __restrict__ inp_out) {
    int bt = blockIdx.x;
    int n  = threadIdx.x;
    __shared__ float sx[INC];
    if (n < INC) sx[n] = x[(size_t)bt * INC + n];
    __syncthreads();

    const float4* w4 = reinterpret_cast<const float4*>(inw + (size_t)n * INC);
    float acc = 0.0f;
#pragma unroll
    for (int i = 0; i < 4; i++) {
        float4 w = __ldg(&w4[i]);
        acc = fmaf(w.x, sx[4 * i + 0], acc);
        acc = fmaf(w.y, sx[4 * i + 1], acc);
        acc = fmaf(w.z, sx[4 * i + 2], acc);
        acc = fmaf(w.w, sx[4 * i + 3], acc);
    }
    inp_out[(size_t)bt * NN + n] = acc;
}

// ---------------------------------------------------------------------------
// Kernel B: the sequential scan. One CTA per batch, 256 threads, 2 n per thread.
// hid[b,t,:] holds Inp[b,t,:] on entry; each step reads it, computes h_t, and
// overwrites the slot (per-thread read-before-write, same element).
// Per step:
//   phi = tanh(h)                          (registers)
//   low[r] = sum_n phi[n] * V_w[r,n]       (reg partials + fold-shuffle + smem)
//   rec[n] = sum_r low[r] * U_w[n,r]       (registers)
//   h = 0.9 h + 0.1 (rec + inp[t])
// ---------------------------------------------------------------------------
__global__ __launch_bounds__(256, 1) void scan_kernel(const float* __restrict__ Vw,
                                                      const float* __restrict__ Uw,
                                                      const float* __restrict__ h0,
                                                      float* hid) {
    const int b    = blockIdx.x;
    const int tid  = threadIdx.x;
    const int lane = tid & 31;
    const int warp = tid >> 5;
    const int n0   = tid * 2;

    // double-buffered per-warp partial sums -> only one __syncthreads per step
    __shared__ float s_wsum[2][8][16];

    // V columns for my two n (16 regs each)
    float v0[RR], v1[RR];
#pragma unroll
    for (int k = 0; k < RR; k++) {
        v0[k] = Vw[k * NN + n0];
        v1[k] = Vw[k * NN + n0 + 1];
    }
    // U rows for my two n
    float u0[RR], u1[RR];
    {
        const float4* a4 = reinterpret_cast<const float4*>(Uw + (size_t)n0 * RR);
        const float4* b4 = reinterpret_cast<const float4*>(Uw + (size_t)(n0 + 1) * RR);
#pragma unroll
        for (int i = 0; i < 4; i++) {
            float4 a = a4[i];
            u0[4 * i + 0] = a.x; u0[4 * i + 1] = a.y; u0[4 * i + 2] = a.z; u0[4 * i + 3] = a.w;
            float4 c = b4[i];
            u1[4 * i + 0] = c.x; u1[4 * i + 1] = c.y; u1[4 * i + 2] = c.z; u1[4 * i + 3] = c.w;
        }
    }

    float h0v = h0[n0];
    float h1v = h0[n0 + 1];

    // hid viewed as float2, one slot per thread per step (coalesced).
    float2* hp = reinterpret_cast<float2*>(hid) + (size_t)b * TT * (NN / 2) + tid;

    for (int s = 0; s < TT; s++) {
        // load this step's input projection (same slot we will store h into)
        float2 iv = hp[(size_t)s * (NN / 2)];

        float ph0 = fast_tanh(h0v);
        float ph1 = fast_tanh(h1v);

        // partials for low[0..15]
        float p[RR];
#pragma unroll
        for (int k = 0; k < RR; k++)
            p[k] = fmaf(ph1, v1[k], ph0 * v0[k]);

        // log-fold reduction: 16 values x 32 lanes -> each lane holds one fully
        // warp-summed output, output index = (lane>>1)&15. Only 16 SHFLs.
        const unsigned FULL = 0xFFFFFFFFu;
#pragma unroll
        for (int j = 0; j < 8; j++) {
            bool hi = (lane & 16) != 0;
            float keep = hi ? p[j + 8] : p[j];
            float send = hi ? p[j] : p[j + 8];
            p[j] = keep + __shfl_xor_sync(FULL, send, 16);
        }
#pragma unroll
        for (int j = 0; j < 4; j++) {
            bool hi = (lane & 8) != 0;
            float keep = hi ? p[j + 4] : p[j];
            float send = hi ? p[j] : p[j + 4];
            p[j] = keep + __shfl_xor_sync(FULL, send, 8);
        }
#pragma unroll
        for (int j = 0; j < 2; j++) {
            bool hi = (lane & 4) != 0;
            float keep = hi ? p[j + 2] : p[j];
            float send = hi ? p[j] : p[j + 2];
            p[j] = keep + __shfl_xor_sync(FULL, send, 4);
        }
        {
            bool hi = (lane & 2) != 0;
            float keep = hi ? p[1] : p[0];
            float send = hi ? p[0] : p[1];
            p[0] = keep + __shfl_xor_sync(FULL, send, 2);
        }
        p[0] += __shfl_xor_sync(FULL, p[0], 1);

        const int buf = s & 1;
        if ((lane & 1) == 0) s_wsum[buf][warp][(lane >> 1) & 15] = p[0];
        __syncthreads();

        // every warp combines the 8 per-warp sums for output k = lane&15,
        // then broadcasts low[r] via shfl (no second barrier needed; the
        // double buffer keeps next step's writes off this buffer).
        const int k = lane & 15;
        float acc = s_wsum[buf][0][k];
#pragma unroll
        for (int w = 1; w < 8; w++) acc += s_wsum[buf][w][k];

        float low[RR];
#pragma unroll
        for (int r = 0; r < RR; r++) low[r] = __shfl_sync(FULL, acc, r);

        // rec = U @ low for my two n (split accumulators for ILP)
        float ra = 0.f, rb = 0.f, rc = 0.f, rd = 0.f;
#pragma unroll
        for (int r = 0; r < RR; r += 2) {
            ra = fmaf(low[r],     u0[r],     ra);
            rc = fmaf(low[r + 1], u0[r + 1], rc);
            rb = fmaf(low[r],     u1[r],     rb);
            rd = fmaf(low[r + 1], u1[r + 1], rd);
        }
        float rec0 = ra + rc;
        float rec1 = rb + rd;

        h0v = fmaf(1.0f - AA, h0v, AA * (rec0 + iv.x));
        h1v = fmaf(1.0f - AA, h1v, AA * (rec1 + iv.y));

        hp[(size_t)s * (NN / 2)] = make_float2(h0v, h1v);
    }
}

// ---------------------------------------------------------------------------
// Kernel C: out[b,t,o] = sum_n tanh(hidden[b,t,n]) * Out_w[o,n]
// warp per (b,t) row; Out_w staged in smem; coalesced float4 hidden reads;
// 8-value fold-shuffle reduction (9 SHFLs).
// ---------------------------------------------------------------------------
__global__ __launch_bounds__(256) void out_kernel(const float* __restrict__ hid,
                                                  const float* __restrict__ Ow,
                                                  float* __restrict__ outp) {
    __shared__ float4 s_w[OUTC * NN / 4];  // 16 KB
    const int tid  = threadIdx.x;
    const int lane = tid & 31;
    const int warp = tid >> 5;

    const float4* ow4 = reinterpret_cast<const float4*>(Ow);
    for (int i = tid; i < OUTC * NN / 4; i += 256) s_w[i] = ow4[i];
    __syncthreads();

    const size_t row = (size_t)blockIdx.x * 8 + warp;  // < B*T
    const float4* h4 = reinterpret_cast<const float4*>(hid) + row * (NN / 4);

    float acc[OUTC];
#pragma unroll
    for (int o = 0; o < OUTC; o++) acc[o] = 0.0f;

#pragma unroll
    for (int i = 0; i < 4; i++) {
        float4 hv = __ldg(&h4[i * 32 + lane]);
        float t0 = fast_tanh(hv.x);
        float t1 = fast_tanh(hv.y);
        float t2 = fast_tanh(hv.z);
        float t3 = fast_tanh(hv.w);
#pragma unroll
        for (int o = 0; o < OUTC; o++) {
            float4 wv = s_w[o * (NN / 4) + i * 32 + lane];
            acc[o] = fmaf(t0, wv.x, fmaf(t1, wv.y, fmaf(t2, wv.z, fmaf(t3, wv.w, acc[o]))));
        }
    }

    // fold 8 values over 32 lanes -> lane holds output (lane>>2)&7
    const unsigned FULL = 0xFFFFFFFFu;
#pragma unroll
    for (int j = 0; j < 4; j++) {
        bool hi = (lane & 16) != 0;
        float keep = hi ? acc[j + 4] : acc[j];
        float send = hi ? acc[j] : acc[j + 4];
        acc[j] = keep + __shfl_xor_sync(FULL, send, 16);
    }
#pragma unroll
    for (int j = 0; j < 2; j++) {
        bool hi = (lane & 8) != 0;
        float keep = hi ? acc[j + 2] : acc[j];
        float send = hi ? acc[j] : acc[j + 2];
        acc[j] = keep + __shfl_xor_sync(FULL, send, 8);
    }
    {
        bool hi = (lane & 4) != 0;
        float keep = hi ? acc[1] : acc[0];
        float send = hi ? acc[0] : acc[1];
        acc[0] = keep + __shfl_xor_sync(FULL, send, 4);
    }
    acc[0] += __shfl_xor_sync(FULL, acc[0], 2);
    acc[0] += __shfl_xor_sync(FULL, acc[0], 1);

    if ((lane & 3) == 0)
        outp[row * OUTC + ((lane >> 2) & 7)] = acc[0];
}

// ---------------------------------------------------------------------------
// kernel_launch: inputs per metadata order:
//   0 Batch_Input [B,T,INC], 1 In_w [N,INC], 2 V_w [R,N], 3 U_w [N,R],
//   4 Out_w [OUTC,N], 5 hidden_0 [N]
// d_out: hidden_t [B,T,N] followed by out [B,T,OUTC]  (float32)
// ---------------------------------------------------------------------------
extern "C" void kernel_launch(void* const* d_in, const int* in_sizes, int n_in,
                              void* d_out, int out_size) {
    const float* x   = (const float*)d_in[0];
    const float* inw = (const float*)d_in[1];
    const float* vw  = (const float*)d_in[2];
    const float* uw  = (const float*)d_in[3];
    const float* ow  = (const float*)d_in[4];
    const float* h0  = (const float*)d_in[5];

    float* hid  = (float*)d_out;
    float* outp = hid + (size_t)BB * TT * NN;

    inp_kernel<<<BB * TT, NN>>>(x, inw, hid);   // Inp staged into hid region
    scan_kernel<<<BB, 256>>>(vw, uw, h0, hid);  // reads Inp, overwrites with h
    out_kernel<<<BB * TT / 8, 256>>>(hid, ow, outp);
}

// round 7
// speedup vs baseline: 1.6992x; 1.6992x over previous
#include <cuda_runtime.h>
#include <cstdint>

// Problem constants (fixed by the reference setup)
#define BB   64
#define TT   1024
#define INC  16
#define NN   512
#define RR   16
#define OUTC 8
#define AA   0.1f   // DT / TAU

// Accurate-enough fast tanh: 1 - 2/(exp(2x)+1) via ex2.approx + rcp.approx.
// Error ~1e-6 (vs ~5e-4 for tanh.approx), safe for 1024-step recurrence.
__device__ __forceinline__ float fast_tanh(float x) {
    float e;
    asm("ex2.approx.f32 %0, %1;" : "=f"(e) : "f"(x * 2.885390082f)); // 2*log2(e)
    float r;
    asm("rcp.approx.f32 %0, %1;" : "=f"(r) : "f"(e + 1.0f));
    return fmaf(-2.0f, r, 1.0f);
}

// ---------------------------------------------------------------------------
// Kernel A (v2): Inp[b,t,n] = sum_i X[b,t,i] * In_w[n,i], written into the
// hidden region of d_out (scratch aliasing with the scan).
// Tiled: each block owns 64 (b,t)-rows and all 512 n. In_w rows live in
// registers (loaded ONCE per block), X tile staged in smem, broadcast LDS.
// This removes the 134M redundant In_w L1 fetches of v1 (was 97% L1-bound).
// ---------------------------------------------------------------------------
#define IROWS 64
__global__ __launch_bounds__(256) void inp_kernel(const float* __restrict__ x,
                                                  const float* __restrict__ inw,
                                                  float* __restrict__ inp_out) {
    const int tid = threadIdx.x;
    const int r0  = blockIdx.x * IROWS;          // first bt row of this block
    __shared__ float4 sx4[IROWS * INC / 4];      // 64 rows x 16 floats = 4KB

    // stage X tile: 1024 contiguous floats = 256 float4, one per thread
    sx4[tid] = reinterpret_cast<const float4*>(x)[(size_t)r0 * (INC / 4) + tid];

    // my two In_w rows -> registers (one-time cost per block)
    const int n0 = tid * 2;
    float w0[INC], w1[INC];
    {
        const float4* a4 = reinterpret_cast<const float4*>(inw + (size_t)n0 * INC);
        const float4* b4 = reinterpret_cast<const float4*>(inw + (size_t)(n0 + 1) * INC);
#pragma unroll
        for (int i = 0; i < 4; i++) {
            float4 a = __ldg(&a4[i]);
            w0[4 * i + 0] = a.x; w0[4 * i + 1] = a.y; w0[4 * i + 2] = a.z; w0[4 * i + 3] = a.w;
            float4 c = __ldg(&b4[i]);
            w1[4 * i + 0] = c.x; w1[4 * i + 1] = c.y; w1[4 * i + 2] = c.z; w1[4 * i + 3] = c.w;
        }
    }
    __syncthreads();

    float2* out2 = reinterpret_cast<float2*>(inp_out) + (size_t)r0 * (NN / 2) + tid;

#pragma unroll 4
    for (int j = 0; j < IROWS; j++) {
        float acc0 = 0.0f, acc1 = 0.0f;
#pragma unroll
        for (int q = 0; q < 4; q++) {
            float4 xv = sx4[j * 4 + q];          // broadcast across all threads
            acc0 = fmaf(w0[4 * q + 0], xv.x, acc0);
            acc0 = fmaf(w0[4 * q + 1], xv.y, acc0);
            acc0 = fmaf(w0[4 * q + 2], xv.z, acc0);
            acc0 = fmaf(w0[4 * q + 3], xv.w, acc0);
            acc1 = fmaf(w1[4 * q + 0], xv.x, acc1);
            acc1 = fmaf(w1[4 * q + 1], xv.y, acc1);
            acc1 = fmaf(w1[4 * q + 2], xv.z, acc1);
            acc1 = fmaf(w1[4 * q + 3], xv.w, acc1);
        }
        out2[(size_t)j * (NN / 2)] = make_float2(acc0, acc1);
    }
}

// ---------------------------------------------------------------------------
// Kernel B: the sequential scan. One CTA per batch, 256 threads, 2 n per thread.
// hid[b,t,:] holds Inp[b,t,:] on entry; each step consumes it and overwrites
// the slot with h_t. The Inp load is software-pipelined 2 steps ahead so its
// DRAM latency (~600+ cyc) is off the serial critical path. Pipelining is
// alias-safe: slot s+2 is read at iteration s and only written at iteration
// s+2, all by the same thread.
// ---------------------------------------------------------------------------
__global__ __launch_bounds__(256, 1) void scan_kernel(const float* __restrict__ Vw,
                                                      const float* __restrict__ Uw,
                                                      const float* __restrict__ h0,
                                                      float* hid) {
    const int b    = blockIdx.x;
    const int tid  = threadIdx.x;
    const int lane = tid & 31;
    const int warp = tid >> 5;
    const int n0   = tid * 2;

    // double-buffered per-warp partial sums -> only one __syncthreads per step
    __shared__ float s_wsum[2][8][16];

    // V columns for my two n (16 regs each)
    float v0[RR], v1[RR];
#pragma unroll
    for (int k = 0; k < RR; k++) {
        v0[k] = Vw[k * NN + n0];
        v1[k] = Vw[k * NN + n0 + 1];
    }
    // U rows for my two n
    float u0[RR], u1[RR];
    {
        const float4* a4 = reinterpret_cast<const float4*>(Uw + (size_t)n0 * RR);
        const float4* b4 = reinterpret_cast<const float4*>(Uw + (size_t)(n0 + 1) * RR);
#pragma unroll
        for (int i = 0; i < 4; i++) {
            float4 a = a4[i];
            u0[4 * i + 0] = a.x; u0[4 * i + 1] = a.y; u0[4 * i + 2] = a.z; u0[4 * i + 3] = a.w;
            float4 c = b4[i];
            u1[4 * i + 0] = c.x; u1[4 * i + 1] = c.y; u1[4 * i + 2] = c.z; u1[4 * i + 3] = c.w;
        }
    }

    float h0v = h0[n0];
    float h1v = h0[n0 + 1];

    // hid viewed as float2, one slot per thread per step (coalesced).
    float2* hp = reinterpret_cast<float2*>(hid) + (size_t)b * TT * (NN / 2) + tid;
    const size_t STRD = NN / 2;

    // prime the 2-deep inp pipeline
    float2 iv_a = __ldg(&hp[0]);
    float2 iv_b = __ldg(&hp[STRD]);

    for (int s = 0; s < TT; s++) {
        // issue load for step s+2 (clamped; consumed two iterations from now)
        const int sp = (s + 2 < TT) ? (s + 2) : (TT - 1);
        float2 iv_c = __ldg(&hp[(size_t)sp * STRD]);

        float ph0 = fast_tanh(h0v);
        float ph1 = fast_tanh(h1v);

        // partials for low[0..15]
        float p[RR];
#pragma unroll
        for (int k = 0; k < RR; k++)
            p[k] = fmaf(ph1, v1[k], ph0 * v0[k]);

        // log-fold reduction: 16 values x 32 lanes -> each lane holds one fully
        // warp-summed output, output index = (lane>>1)&15. Only 16 SHFLs.
        const unsigned FULL = 0xFFFFFFFFu;
#pragma unroll
        for (int j = 0; j < 8; j++) {
            bool hi = (lane & 16) != 0;
            float keep = hi ? p[j + 8] : p[j];
            float send = hi ? p[j] : p[j + 8];
            p[j] = keep + __shfl_xor_sync(FULL, send, 16);
        }
#pragma unroll
        for (int j = 0; j < 4; j++) {
            bool hi = (lane & 8) != 0;
            float keep = hi ? p[j + 4] : p[j];
            float send = hi ? p[j] : p[j + 4];
            p[j] = keep + __shfl_xor_sync(FULL, send, 8);
        }
#pragma unroll
        for (int j = 0; j < 2; j++) {
            bool hi = (lane & 4) != 0;
            float keep = hi ? p[j + 2] : p[j];
            float send = hi ? p[j] : p[j + 2];
            p[j] = keep + __shfl_xor_sync(FULL, send, 4);
        }
        {
            bool hi = (lane & 2) != 0;
            float keep = hi ? p[1] : p[0];
            float send = hi ? p[0] : p[1];
            p[0] = keep + __shfl_xor_sync(FULL, send, 2);
        }
        p[0] += __shfl_xor_sync(FULL, p[0], 1);

        const int buf = s & 1;
        if ((lane & 1) == 0) s_wsum[buf][warp][(lane >> 1) & 15] = p[0];
        __syncthreads();

        // cross-warp combine (latency-balanced tree of 8 LDS values),
        // then broadcast low[r] via shfl (double buffer removes 2nd barrier).
        const int k = lane & 15;
        float a01 = s_wsum[buf][0][k] + s_wsum[buf][1][k];
        float a23 = s_wsum[buf][2][k] + s_wsum[buf][3][k];
        float a45 = s_wsum[buf][4][k] + s_wsum[buf][5][k];
        float a67 = s_wsum[buf][6][k] + s_wsum[buf][7][k];
        float acc = (a01 + a23) + (a45 + a67);

        float low[RR];
#pragma unroll
        for (int r = 0; r < RR; r++) low[r] = __shfl_sync(FULL, acc, r);

        // rec = U @ low for my two n (split accumulators for ILP)
        float ra = 0.f, rb = 0.f, rc = 0.f, rd = 0.f;
#pragma unroll
        for (int r = 0; r < RR; r += 2) {
            ra = fmaf(low[r],     u0[r],     ra);
            rc = fmaf(low[r + 1], u0[r + 1], rc);
            rb = fmaf(low[r],     u1[r],     rb);
            rd = fmaf(low[r + 1], u1[r + 1], rd);
        }
        float rec0 = ra + rc;
        float rec1 = rb + rd;

        h0v = fmaf(1.0f - AA, h0v, AA * (rec0 + iv_a.x));
        h1v = fmaf(1.0f - AA, h1v, AA * (rec1 + iv_a.y));

        hp[(size_t)s * STRD] = make_float2(h0v, h1v);

        iv_a = iv_b;
        iv_b = iv_c;
    }
}

// ---------------------------------------------------------------------------
// Kernel C: out[b,t,o] = sum_n tanh(hidden[b,t,n]) * Out_w[o,n]
// warp per (b,t) row; Out_w staged in smem; coalesced float4 hidden reads;
// 8-value fold-shuffle reduction (9 SHFLs).
// ---------------------------------------------------------------------------
__global__ __launch_bounds__(256) void out_kernel(const float* __restrict__ hid,
                                                  const float* __restrict__ Ow,
                                                  float* __restrict__ outp) {
    __shared__ float4 s_w[OUTC * NN / 4];  // 16 KB
    const int tid  = threadIdx.x;
    const int lane = tid & 31;
    const int warp = tid >> 5;

    const float4* ow4 = reinterpret_cast<const float4*>(Ow);
    for (int i = tid; i < OUTC * NN / 4; i += 256) s_w[i] = ow4[i];
    __syncthreads();

    const size_t row = (size_t)blockIdx.x * 8 + warp;  // < B*T
    const float4* h4 = reinterpret_cast<const float4*>(hid) + row * (NN / 4);

    float acc[OUTC];
#pragma unroll
    for (int o = 0; o < OUTC; o++) acc[o] = 0.0f;

#pragma unroll
    for (int i = 0; i < 4; i++) {
        float4 hv = __ldg(&h4[i * 32 + lane]);
        float t0 = fast_tanh(hv.x);
        float t1 = fast_tanh(hv.y);
        float t2 = fast_tanh(hv.z);
        float t3 = fast_tanh(hv.w);
#pragma unroll
        for (int o = 0; o < OUTC; o++) {
            float4 wv = s_w[o * (NN / 4) + i * 32 + lane];
            acc[o] = fmaf(t0, wv.x, fmaf(t1, wv.y, fmaf(t2, wv.z, fmaf(t3, wv.w, acc[o]))));
        }
    }

    // fold 8 values over 32 lanes -> lane holds output (lane>>2)&7
    const unsigned FULL = 0xFFFFFFFFu;
#pragma unroll
    for (int j = 0; j < 4; j++) {
        bool hi = (lane & 16) != 0;
        float keep = hi ? acc[j + 4] : acc[j];
        float send = hi ? acc[j] : acc[j + 4];
        acc[j] = keep + __shfl_xor_sync(FULL, send, 16);
    }
#pragma unroll
    for (int j = 0; j < 2; j++) {
        bool hi = (lane & 8) != 0;
        float keep = hi ? acc[j + 2] : acc[j];
        float send = hi ? acc[j] : acc[j + 2];
        acc[j] = keep + __shfl_xor_sync(FULL, send, 8);
    }
    {
        bool hi = (lane & 4) != 0;
        float keep = hi ? acc[1] : acc[0];
        float send = hi ? acc[0] : acc[1];
        acc[0] = keep + __shfl_xor_sync(FULL, send, 4);
    }
    acc[0] += __shfl_xor_sync(FULL, acc[0], 2);
    acc[0] += __shfl_xor_sync(FULL, acc[0], 1);

    if ((lane & 3) == 0)
        outp[row * OUTC + ((lane >> 2) & 7)] = acc[0];
}

// ---------------------------------------------------------------------------
// kernel_launch: inputs per metadata order:
//   0 Batch_Input [B,T,INC], 1 In_w [N,INC], 2 V_w [R,N], 3 U_w [N,R],
//   4 Out_w [OUTC,N], 5 hidden_0 [N]
// d_out: hidden_t [B,T,N] followed by out [B,T,OUTC]  (float32)
// ---------------------------------------------------------------------------
extern "C" void kernel_launch(void* const* d_in, const int* in_sizes, int n_in,
                              void* d_out, int out_size) {
    const float* x   = (const float*)d_in[0];
    const float* inw = (const float*)d_in[1];
    const float* vw  = (const float*)d_in[2];
    const float* uw  = (const float*)d_in[3];
    const float* ow  = (const float*)d_in[4];
    const float* h0  = (const float*)d_in[5];

    float* hid  = (float*)d_out;
    float* outp = hid + (size_t)BB * TT * NN;

    inp_kernel<<<BB * TT / IROWS, 256>>>(x, inw, hid);  // Inp staged into hid
    scan_kernel<<<BB, 256>>>(vw, uw, h0, hid);          // reads Inp, writes h
    out_kernel<<<BB * TT / 8, 256>>>(hid, ow, outp);
}

// round 8
// speedup vs baseline: 1.7377x; 1.0227x over previous
#include <cuda_runtime.h>
#include <cstdint>

// Problem constants (fixed by the reference setup)
#define BB   64
#define TT   1024
#define INC  16
#define NN   512
#define RR   16
#define OUTC 8
#define AA   0.1f   // DT / TAU

typedef unsigned long long u64;

// ---------------- packed f32x2 helpers (sm_103a dual-fp32 pipe) --------------
__device__ __forceinline__ u64 pk2(float lo, float hi) {
    u64 r; asm("mov.b64 %0, {%1, %2};" : "=l"(r) : "f"(lo), "f"(hi)); return r;
}
__device__ __forceinline__ void upk2(u64 v, float& lo, float& hi) {
    asm("mov.b64 {%0, %1}, %2;" : "=f"(lo), "=f"(hi) : "l"(v));
}
__device__ __forceinline__ u64 fma2(u64 a, u64 b, u64 c) {
    u64 d; asm("fma.rn.f32x2 %0, %1, %2, %3;" : "=l"(d) : "l"(a), "l"(b), "l"(c)); return d;
}
__device__ __forceinline__ u64 mul2(u64 a, u64 b) {
    u64 d; asm("mul.rn.f32x2 %0, %1, %2;" : "=l"(d) : "l"(a), "l"(b)); return d;
}
__device__ __forceinline__ u64 add2(u64 a, u64 b) {
    u64 d; asm("add.rn.f32x2 %0, %1, %2;" : "=l"(d) : "l"(a), "l"(b)); return d;
}

// Accurate-enough fast tanh: 1 - 2/(exp(2x)+1) via ex2.approx + rcp.approx.
__device__ __forceinline__ float fast_tanh(float x) {
    float e;
    asm("ex2.approx.f32 %0, %1;" : "=f"(e) : "f"(x * 2.885390082f)); // 2*log2(e)
    float r;
    asm("rcp.approx.f32 %0, %1;" : "=f"(r) : "f"(e + 1.0f));
    return fmaf(-2.0f, r, 1.0f);
}

// ---------------------------------------------------------------------------
// Kernel A: Inp[b,t,n] = sum_i X[b,t,i] * In_w[n,i], written into the hidden
// region of d_out (scratch aliasing with the scan). Tiled, In_w in registers.
// ---------------------------------------------------------------------------
#define IROWS 64
__global__ __launch_bounds__(256) void inp_kernel(const float* __restrict__ x,
                                                  const float* __restrict__ inw,
                                                  float* __restrict__ inp_out) {
    const int tid = threadIdx.x;
    const int r0  = blockIdx.x * IROWS;
    __shared__ float4 sx4[IROWS * INC / 4];

    sx4[tid] = reinterpret_cast<const float4*>(x)[(size_t)r0 * (INC / 4) + tid];

    const int n0 = tid * 2;
    float w0[INC], w1[INC];
    {
        const float4* a4 = reinterpret_cast<const float4*>(inw + (size_t)n0 * INC);
        const float4* b4 = reinterpret_cast<const float4*>(inw + (size_t)(n0 + 1) * INC);
#pragma unroll
        for (int i = 0; i < 4; i++) {
            float4 a = __ldg(&a4[i]);
            w0[4 * i + 0] = a.x; w0[4 * i + 1] = a.y; w0[4 * i + 2] = a.z; w0[4 * i + 3] = a.w;
            float4 c = __ldg(&b4[i]);
            w1[4 * i + 0] = c.x; w1[4 * i + 1] = c.y; w1[4 * i + 2] = c.z; w1[4 * i + 3] = c.w;
        }
    }
    __syncthreads();

    float2* out2 = reinterpret_cast<float2*>(inp_out) + (size_t)r0 * (NN / 2) + tid;

#pragma unroll 4
    for (int j = 0; j < IROWS; j++) {
        float acc0 = 0.0f, acc1 = 0.0f;
#pragma unroll
        for (int q = 0; q < 4; q++) {
            float4 xv = sx4[j * 4 + q];
            acc0 = fmaf(w0[4 * q + 0], xv.x, acc0);
            acc0 = fmaf(w0[4 * q + 1], xv.y, acc0);
            acc0 = fmaf(w0[4 * q + 2], xv.z, acc0);
            acc0 = fmaf(w0[4 * q + 3], xv.w, acc0);
            acc1 = fmaf(w1[4 * q + 0], xv.x, acc1);
            acc1 = fmaf(w1[4 * q + 1], xv.y, acc1);
            acc1 = fmaf(w1[4 * q + 2], xv.z, acc1);
            acc1 = fmaf(w1[4 * q + 3], xv.w, acc1);
        }
        out2[(size_t)j * (NN / 2)] = make_float2(acc0, acc1);
    }
}

// ---------------------------------------------------------------------------
// Kernel B (v3): the sequential scan, packed-f32x2 edition.
// One CTA per batch, 256 threads, 2 n per thread. hid[b,t,:] holds Inp on
// entry (consumed, then overwritten with h_t). Inp prefetched 2 steps ahead.
//
// Per step per thread:
//   tanh x2 (scalar MUFU)
//   P[j] (8 packed regs = partials for low[2j],low[2j+1]): 8 mul2 + 8 fma2
//   packed fold: 7 sel-folds + 2 tail folds, ~18 SHFL, 9 add2
//   lanes (lane&3)==0 STS packed warp-sum; __syncthreads
//   lanes 0..7: cross-warp combine (8 LDS.64 + 7 add2) -> s_low[warp]
//   __syncwarp; 4x LDS.128 broadcast -> LOW[8] packed
//   rec: 2n x (8 fma2-class) + horizontal adds; h update; STG.64
// ---------------------------------------------------------------------------
__global__ __launch_bounds__(256, 1) void scan_kernel(const float* __restrict__ Vw,
                                                      const float* __restrict__ Uw,
                                                      const float* __restrict__ h0,
                                                      float* hid) {
    const int b    = blockIdx.x;
    const int tid  = threadIdx.x;
    const int lane = tid & 31;
    const int warp = tid >> 5;
    const int n0   = tid * 2;

    __shared__ u64 s_wsum[2][8][8];   // [buf][warp][packed low pair]
    __shared__ u64 s_low[8][8];       // [warp][packed low pair]

    // V packed over r-pairs: V0[j] = (Vw[2j][n0], Vw[2j+1][n0])
    u64 V0[8], V1[8];
#pragma unroll
    for (int j = 0; j < 8; j++) {
        V0[j] = pk2(Vw[(2 * j) * NN + n0],     Vw[(2 * j + 1) * NN + n0]);
        V1[j] = pk2(Vw[(2 * j) * NN + n0 + 1], Vw[(2 * j + 1) * NN + n0 + 1]);
    }
    // U rows are contiguous in r: load pairs directly (128B-aligned)
    u64 U0[8], U1[8];
    {
        const u64* up = reinterpret_cast<const u64*>(Uw + (size_t)n0 * RR);
#pragma unroll
        for (int j = 0; j < 8; j++) { U0[j] = up[j]; U1[j] = up[8 + j]; }
    }

    float h0v = h0[n0];
    float h1v = h0[n0 + 1];

    float2* hp = reinterpret_cast<float2*>(hid) + (size_t)b * TT * (NN / 2) + tid;
    const size_t STRD = NN / 2;

    float2 iv_a = __ldg(&hp[0]);
    float2 iv_b = __ldg(&hp[STRD]);

    const unsigned FULL = 0xFFFFFFFFu;

    for (int s = 0; s < TT; s++) {
        const int sp = (s + 2 < TT) ? (s + 2) : (TT - 1);
        float2 iv_c = __ldg(&hp[(size_t)sp * STRD]);

        float ph0 = fast_tanh(h0v);
        float ph1 = fast_tanh(h1v);
        u64 PH0 = pk2(ph0, ph0);
        u64 PH1 = pk2(ph1, ph1);

        // partials: P[j] holds (low[2j],low[2j+1]) contribution of my 2 n
        u64 P[8];
#pragma unroll
        for (int j = 0; j < 8; j++)
            P[j] = fma2(PH1, V1[j], mul2(PH0, V0[j]));

        // packed fold over lane bits 16,8,4 (j-dim 8->1), then bits 2,1 tails.
        // Survivor at lane L: packed outputs (2a, 2a+1), a = (L>>2)&7.
#pragma unroll
        for (int j = 0; j < 4; j++) {
            bool hi = (lane & 16) != 0;
            u64 keep = hi ? P[j + 4] : P[j];
            u64 send = hi ? P[j] : P[j + 4];
            P[j] = add2(keep, __shfl_xor_sync(FULL, send, 16));
        }
#pragma unroll
        for (int j = 0; j < 2; j++) {
            bool hi = (lane & 8) != 0;
            u64 keep = hi ? P[j + 2] : P[j];
            u64 send = hi ? P[j] : P[j + 2];
            P[j] = add2(keep, __shfl_xor_sync(FULL, send, 8));
        }
        {
            bool hi = (lane & 4) != 0;
            u64 keep = hi ? P[1] : P[0];
            u64 send = hi ? P[0] : P[1];
            P[0] = add2(keep, __shfl_xor_sync(FULL, send, 4));
        }
        P[0] = add2(P[0], __shfl_xor_sync(FULL, P[0], 2));
        P[0] = add2(P[0], __shfl_xor_sync(FULL, P[0], 1));

        const int buf = s & 1;
        if ((lane & 3) == 0) s_wsum[buf][warp][(lane >> 2) & 7] = P[0];
        __syncthreads();

        // cross-warp combine: lanes 0..7 sum 8 warp values for packed pair a=lane
        if (lane < 8) {
            u64 a01 = add2(s_wsum[buf][0][lane], s_wsum[buf][1][lane]);
            u64 a23 = add2(s_wsum[buf][2][lane], s_wsum[buf][3][lane]);
            u64 a45 = add2(s_wsum[buf][4][lane], s_wsum[buf][5][lane]);
            u64 a67 = add2(s_wsum[buf][6][lane], s_wsum[buf][7][lane]);
            s_low[warp][lane] = add2(add2(a01, a23), add2(a45, a67));
        }
        __syncwarp();

        // broadcast low[16] back as 4x LDS.128 (per-warp slot, conflict-free)
        u64 LOW[8];
        {
            const ulonglong2* lp = reinterpret_cast<const ulonglong2*>(s_low[warp]);
#pragma unroll
            for (int q = 0; q < 4; q++) {
                ulonglong2 t = lp[q];
                LOW[2 * q]     = t.x;
                LOW[2 * q + 1] = t.y;
            }
        }

        // rec = U @ low for my two n, packed over r-pairs (2 accs each for ILP)
        u64 a0 = mul2(LOW[0], U0[0]), b0 = mul2(LOW[1], U0[1]);
        u64 a1 = mul2(LOW[0], U1[0]), b1 = mul2(LOW[1], U1[1]);
#pragma unroll
        for (int j = 2; j < 8; j += 2) {
            a0 = fma2(LOW[j],     U0[j],     a0);
            b0 = fma2(LOW[j + 1], U0[j + 1], b0);
            a1 = fma2(LOW[j],     U1[j],     a1);
            b1 = fma2(LOW[j + 1], U1[j + 1], b1);
        }
        float r0l, r0h, r1l, r1h;
        upk2(add2(a0, b0), r0l, r0h);
        upk2(add2(a1, b1), r1l, r1h);
        float rec0 = r0l + r0h;
        float rec1 = r1l + r1h;

        h0v = fmaf(1.0f - AA, h0v, AA * (rec0 + iv_a.x));
        h1v = fmaf(1.0f - AA, h1v, AA * (rec1 + iv_a.y));

        hp[(size_t)s * STRD] = make_float2(h0v, h1v);

        iv_a = iv_b;
        iv_b = iv_c;
    }
}

// ---------------------------------------------------------------------------
// Kernel C: out[b,t,o] = sum_n tanh(hidden[b,t,n]) * Out_w[o,n]
// warp per (b,t) row; Out_w staged in smem; coalesced float4 hidden reads.
// ---------------------------------------------------------------------------
__global__ __launch_bounds__(256) void out_kernel(const float* __restrict__ hid,
                                                  const float* __restrict__ Ow,
                                                  float* __restrict__ outp) {
    __shared__ float4 s_w[OUTC * NN / 4];  // 16 KB
    const int tid  = threadIdx.x;
    const int lane = tid & 31;
    const int warp = tid >> 5;

    const float4* ow4 = reinterpret_cast<const float4*>(Ow);
    for (int i = tid; i < OUTC * NN / 4; i += 256) s_w[i] = ow4[i];
    __syncthreads();

    const size_t row = (size_t)blockIdx.x * 8 + warp;  // < B*T
    const float4* h4 = reinterpret_cast<const float4*>(hid) + row * (NN / 4);

    float acc[OUTC];
#pragma unroll
    for (int o = 0; o < OUTC; o++) acc[o] = 0.0f;

#pragma unroll
    for (int i = 0; i < 4; i++) {
        float4 hv = __ldg(&h4[i * 32 + lane]);
        float t0 = fast_tanh(hv.x);
        float t1 = fast_tanh(hv.y);
        float t2 = fast_tanh(hv.z);
        float t3 = fast_tanh(hv.w);
#pragma unroll
        for (int o = 0; o < OUTC; o++) {
            float4 wv = s_w[o * (NN / 4) + i * 32 + lane];
            acc[o] = fmaf(t0, wv.x, fmaf(t1, wv.y, fmaf(t2, wv.z, fmaf(t3, wv.w, acc[o]))));
        }
    }

    const unsigned FULL = 0xFFFFFFFFu;
#pragma unroll
    for (int j = 0; j < 4; j++) {
        bool hi = (lane & 16) != 0;
        float keep = hi ? acc[j + 4] : acc[j];
        float send = hi ? acc[j] : acc[j + 4];
        acc[j] = keep + __shfl_xor_sync(FULL, send, 16);
    }
#pragma unroll
    for (int j = 0; j < 2; j++) {
        bool hi = (lane & 8) != 0;
        float keep = hi ? acc[j + 2] : acc[j];
        float send = hi ? acc[j] : acc[j + 2];
        acc[j] = keep + __shfl_xor_sync(FULL, send, 8);
    }
    {
        bool hi = (lane & 4) != 0;
        float keep = hi ? acc[1] : acc[0];
        float send = hi ? acc[0] : acc[1];
        acc[0] = keep + __shfl_xor_sync(FULL, send, 4);
    }
    acc[0] += __shfl_xor_sync(FULL, acc[0], 2);
    acc[0] += __shfl_xor_sync(FULL, acc[0], 1);

    if ((lane & 3) == 0)
        outp[row * OUTC + ((lane >> 2) & 7)] = acc[0];
}

// ---------------------------------------------------------------------------
// kernel_launch: inputs per metadata order:
//   0 Batch_Input [B,T,INC], 1 In_w [N,INC], 2 V_w [R,N], 3 U_w [N,R],
//   4 Out_w [OUTC,N], 5 hidden_0 [N]
// d_out: hidden_t [B,T,N] followed by out [B,T,OUTC]  (float32)
// ---------------------------------------------------------------------------
extern "C" void kernel_launch(void* const* d_in, const int* in_sizes, int n_in,
                              void* d_out, int out_size) {
    const float* x   = (const float*)d_in[0];
    const float* inw = (const float*)d_in[1];
    const float* vw  = (const float*)d_in[2];
    const float* uw  = (const float*)d_in[3];
    const float* ow  = (const float*)d_in[4];
    const float* h0  = (const float*)d_in[5];

    float* hid  = (float*)d_out;
    float* outp = hid + (size_t)BB * TT * NN;

    inp_kernel<<<BB * TT / IROWS, 256>>>(x, inw, hid);  // Inp staged into hid
    scan_kernel<<<BB, 256>>>(vw, uw, h0, hid);          // reads Inp, writes h
    out_kernel<<<BB * TT / 8, 256>>>(hid, ow, outp);
}